// round 1
// baseline (speedup 1.0000x reference)
#include <cuda_runtime.h>

// CornerProposal eval path on GB300.
//
// Reference math collapses exactly:
//   anc_centers = floor(anc_bases[:,:,:2])            (integer-valued fp32)
//   grid_sample(align_corners=False) sample points land at integer - 0.5
//   => fx = fy = 0.5 exactly => pure 2x2 box average, no border cases
//   out[b,n,c,i,j] = 0.25*(I[y-1,x-1]+I[y-1,x]+I[y,x-1]+I[y,x])
//     with y = cy+i-15, x = cx+j-15, all taps guaranteed in [0,222].
//
// One warp per (b,n,c): lane = patch column. Load the 32x32 patch once
// (one LDG per unique tap), reuse rows via registers and the +1 column via
// shfl_down. Stores are 31 consecutive floats per row (coalesced).

static constexpr int B = 8;
static constexpr int N = 600;
static constexpr int C = 32;
static constexpr int H = 256;
static constexpr int W = 256;
static constexpr int G = 31;              // glimpse size
static constexpr int ROIS_ELEMS = B * N * C * G * G;

__global__ __launch_bounds__(256)
void glimpse_kernel(const float* __restrict__ img,
                    const float* __restrict__ anc,
                    float* __restrict__ out)
{
    const int warp = (blockIdx.x * blockDim.x + threadIdx.x) >> 5;
    const int lane = threadIdx.x & 31;

    // warp -> (bn, c); C = 32 (power of two)
    const int c  = warp & (C - 1);
    const int bn = warp >> 5;
    if (bn >= B * N) return;

    // anchor center = floor of (xmin, ymin); exact integer in fp32
    const float ax = __ldg(anc + (size_t)bn * 4 + 0);
    const float ay = __ldg(anc + (size_t)bn * 4 + 1);
    const int cx = (int)floorf(ax);
    const int cy = (int)floorf(ay);

    const int b = bn / N;

    // patch top-left: (cy-16, cx-16); 32 rows x 32 cols, guaranteed in-bounds
    const float* base = img + (((size_t)(b * C + c)) * H + (size_t)(cy - 16)) * W
                            + (cx - 16);

    // Load full 32x32 patch column for this lane — 32 independent LDGs,
    // fully unrolled so ptxas front-batches them (high MLP, mostly L2 hits).
    float r[32];
    #pragma unroll
    for (int i = 0; i < 32; ++i)
        r[i] = __ldg(base + i * W + lane);

    float* o = out + ((size_t)bn * C + c) * (G * G);

    #pragma unroll
    for (int i = 0; i < G; ++i) {
        // vertical pair sum for column (cx-16+lane)
        const float s = r[i] + r[i + 1];
        // horizontal neighbor column from lane+1
        const float t = s + __shfl_down_sync(0xffffffffu, s, 1);
        if (lane < G)
            o[i * G + lane] = 0.25f * t;
    }
}

__global__ void copy_anchors_kernel(const float* __restrict__ anc,
                                    float* __restrict__ out_xy)
{
    const int i = blockIdx.x * blockDim.x + threadIdx.x;   // over B*N
    if (i < B * N) {
        out_xy[2 * i + 0] = anc[(size_t)4 * i + 0];
        out_xy[2 * i + 1] = anc[(size_t)4 * i + 1];
    }
}

extern "C" void kernel_launch(void* const* d_in, const int* in_sizes, int n_in,
                              void* d_out, int out_size)
{
    const float* img = (const float*)d_in[0];   // [B, C, H, W] fp32
    const float* anc = (const float*)d_in[1];   // [B, N, 4]   fp32
    float* out = (float*)d_out;

    // rois first, anchors(:, :, :2) appended — derive tail offset from out_size
    // so we stay correct even if padding differs.
    float* out_xy = out + (out_size - B * N * 2);

    const int total_warps = B * N * C;          // 153600
    const int threads = 256;                    // 8 warps / CTA
    const int blocks = (total_warps * 32 + threads - 1) / threads;

    glimpse_kernel<<<blocks, threads>>>(img, anc, out);

    const int bn = B * N;
    copy_anchors_kernel<<<(bn + 255) / 256, 256>>>(anc, out_xy);

    (void)n_in; (void)in_sizes; (void)out_size;
}